// round 9
// baseline (speedup 1.0000x reference)
#include <cuda_runtime.h>
#include <stdint.h>
#include <math.h>

#define L 512
#define DO 64      // D_ORIG
#define NH 8
#define DH 32
#define DE 256
#define SCALE 0.17677669529663687f  // 1/sqrt(32)

// Scratch (device globals — no allocations allowed)
__device__ float g_q[L*DE];
__device__ float g_k[L*DE];
__device__ float g_v[L*DE];
__device__ float g_p[L*512];            // [i][n*64+c], SCALE folded in
__device__ float g_sc[(size_t)NH*L*L];  // [n][i][j] base qk logits (SCALE folded)

#define CP_ASYNC16(sa, ga) asm volatile("cp.async.cg.shared.global [%0], [%1], 16;\n" :: "r"(sa), "l"(ga))
#define CP_COMMIT()        asm volatile("cp.async.commit_group;\n" ::: "memory")
#define CP_WAIT0()         asm volatile("cp.async.wait_group 0;\n" ::: "memory")

// ---------------------------------------------------------------------------
// Kernel 1: tiled GEMM  {q,k,v}[512x256] = x[512x64] @ W[64x256]
// ---------------------------------------------------------------------------
__global__ void proj_kernel(const float* __restrict__ x, const float* __restrict__ Wq,
                            const float* __restrict__ Wk, const float* __restrict__ Wv) {
    const float* W = (blockIdx.z == 0) ? Wq : (blockIdx.z == 1) ? Wk : Wv;
    float* outp    = (blockIdx.z == 0) ? g_q : (blockIdx.z == 1) ? g_k : g_v;
    int c0 = blockIdx.x * 64, i0 = blockIdx.y * 64;
    int t = threadIdx.x;
    __shared__ __align__(16) float xs[64][68];
    __shared__ __align__(16) float ws[64][68];
    for (int l = t; l < 1024; l += 256) {
        int r = l >> 4, c4 = (l & 15) * 4;
        *(float4*)&xs[r][c4] = *(const float4*)&x[(i0 + r)*DO + c4];
        *(float4*)&ws[r][c4] = *(const float4*)&W[r*DE + c0 + c4];
    }
    __syncthreads();
    int ty = t >> 4, tx = t & 15;
    float acc[4][4] = {};
    #pragma unroll
    for (int k = 0; k < 64; k++) {
        float4 b = *(const float4*)&ws[k][tx*4];
        float a0 = xs[ty*4+0][k], a1 = xs[ty*4+1][k], a2 = xs[ty*4+2][k], a3 = xs[ty*4+3][k];
        acc[0][0] = fmaf(a0, b.x, acc[0][0]); acc[0][1] = fmaf(a0, b.y, acc[0][1]);
        acc[0][2] = fmaf(a0, b.z, acc[0][2]); acc[0][3] = fmaf(a0, b.w, acc[0][3]);
        acc[1][0] = fmaf(a1, b.x, acc[1][0]); acc[1][1] = fmaf(a1, b.y, acc[1][1]);
        acc[1][2] = fmaf(a1, b.z, acc[1][2]); acc[1][3] = fmaf(a1, b.w, acc[1][3]);
        acc[2][0] = fmaf(a2, b.x, acc[2][0]); acc[2][1] = fmaf(a2, b.y, acc[2][1]);
        acc[2][2] = fmaf(a2, b.z, acc[2][2]); acc[2][3] = fmaf(a2, b.w, acc[2][3]);
        acc[3][0] = fmaf(a3, b.x, acc[3][0]); acc[3][1] = fmaf(a3, b.y, acc[3][1]);
        acc[3][2] = fmaf(a3, b.z, acc[3][2]); acc[3][3] = fmaf(a3, b.w, acc[3][3]);
    }
    #pragma unroll
    for (int m = 0; m < 4; m++)
        *(float4*)&outp[(i0 + ty*4 + m)*DE + c0 + tx*4] = *(float4*)&acc[m][0];
}

// ---------------------------------------------------------------------------
// Kernel 1b: p[i][n*64+c] = SCALE * sum_d q[i][n*32+d] * We[c][n*32+d]
// ---------------------------------------------------------------------------
__global__ void p_kernel(const float* __restrict__ We) {
    int i0 = blockIdx.x * 64, n = blockIdx.y;
    int t = threadIdx.x;
    __shared__ __align__(16) float qs[64][36];
    __shared__ __align__(16) float wes[32][68];
    for (int l = t; l < 512; l += 256) {
        int r = l >> 3, d4 = (l & 7) * 4;
        *(float4*)&qs[r][d4] = *(const float4*)&g_q[(i0 + r)*DE + n*DH + d4];
    }
    for (int l = t; l < 512; l += 256) {
        int c = l >> 3, d4 = (l & 7) * 4;
        float4 v4 = *(const float4*)&We[c*DE + n*DH + d4];
        wes[d4 + 0][c] = v4.x; wes[d4 + 1][c] = v4.y;
        wes[d4 + 2][c] = v4.z; wes[d4 + 3][c] = v4.w;
    }
    __syncthreads();
    int ty = t >> 4, tx = t & 15;
    float acc[4][4] = {};
    #pragma unroll
    for (int d = 0; d < 32; d++) {
        float4 b = *(const float4*)&wes[d][tx*4];
        float a0 = qs[ty*4+0][d], a1 = qs[ty*4+1][d], a2 = qs[ty*4+2][d], a3 = qs[ty*4+3][d];
        acc[0][0] = fmaf(a0, b.x, acc[0][0]); acc[0][1] = fmaf(a0, b.y, acc[0][1]);
        acc[0][2] = fmaf(a0, b.z, acc[0][2]); acc[0][3] = fmaf(a0, b.w, acc[0][3]);
        acc[1][0] = fmaf(a1, b.x, acc[1][0]); acc[1][1] = fmaf(a1, b.y, acc[1][1]);
        acc[1][2] = fmaf(a1, b.z, acc[1][2]); acc[1][3] = fmaf(a1, b.w, acc[1][3]);
        acc[2][0] = fmaf(a2, b.x, acc[2][0]); acc[2][1] = fmaf(a2, b.y, acc[2][1]);
        acc[2][2] = fmaf(a2, b.z, acc[2][2]); acc[2][3] = fmaf(a2, b.w, acc[2][3]);
        acc[3][0] = fmaf(a3, b.x, acc[3][0]); acc[3][1] = fmaf(a3, b.y, acc[3][1]);
        acc[3][2] = fmaf(a3, b.z, acc[3][2]); acc[3][3] = fmaf(a3, b.w, acc[3][3]);
    }
    #pragma unroll
    for (int m = 0; m < 4; m++) {
        #pragma unroll
        for (int j = 0; j < 4; j++) acc[m][j] *= SCALE;
        *(float4*)&g_p[(i0 + ty*4 + m)*512 + n*64 + tx*4] = *(float4*)&acc[m][0];
    }
}

// ---------------------------------------------------------------------------
// Kernel 2: base[n][i][j] = scale * q[i,nslice] . k[j,nslice]
// ---------------------------------------------------------------------------
__global__ void qk_kernel() {
    int n = blockIdx.z, i0 = blockIdx.y * 32, j0 = blockIdx.x * 32;
    int t = threadIdx.x;
    __shared__ float Qs[32][33], Ks[32][33];
    for (int l = t; l < 1024; l += 256) {
        int r = l >> 5, d = l & 31;
        Qs[r][d] = g_q[(i0 + r)*DE + n*DH + d];
        Ks[r][d] = g_k[(j0 + r)*DE + n*DH + d];
    }
    __syncthreads();
    int tx = t & 31, ty = t >> 5;
    float acc[4] = {0.f, 0.f, 0.f, 0.f};
    #pragma unroll
    for (int d = 0; d < 32; d++) {
        float kv = Ks[tx][d];
        #pragma unroll
        for (int m = 0; m < 4; m++) acc[m] = fmaf(Qs[ty*4 + m][d], kv, acc[m]);
    }
    #pragma unroll
    for (int m = 0; m < 4; m++)
        g_sc[((size_t)n*L + (i0 + ty*4 + m))*L + j0 + tx] = acc[m] * SCALE;
}

// ---------------------------------------------------------------------------
// Kernel 3 (hot): warp-autonomous fused attention, 128-thr CTA, 32-row tiles.
// Warp w (of 4) owns j-rows w*8..w*8+7 of every tile. No CTA barrier in loop.
// ---------------------------------------------------------------------------
#define TROWS 32
#define TSTRIDE 2176   // 32*68 floats per buffer
__global__ void __launch_bounds__(128, 8)
attn_kernel(const float* __restrict__ e, const float* __restrict__ We,
            const float* __restrict__ Wo, const float* __restrict__ bo,
            float* __restrict__ out) {
    int i = blockIdx.x, t = threadIdx.x;
    int w = t >> 5, lane = t & 31;
    int cq = lane >> 3, jg = lane & 7;    // phase-A: quarter cq, row jg
    int jl = w*8 + jg;                    // local j row owned in phase A (0..31)
    int vh = lane >> 3;                   // head of v-column 4*lane

    __shared__ __align__(16) float espool[2*TSTRIDE]; // [2][32][68]
    __shared__ __align__(16) float ps[512];
    __shared__ __align__(16) float pes[TROWS*8];      // [j_local][head]
    __shared__ __align__(16) float pes_t[8*TROWS];    // [head][j_local]
    __shared__ float svals[NH];

    const float* ebase = e + (size_t)i*L*DO;
    unsigned es_sa = (unsigned)__cvta_generic_to_shared(espool);

    // prologue: warp w prefetches ITS 8 rows of tile 0 into buffer 0
    #pragma unroll
    for (int k2 = 0; k2 < 4; k2++) {
        int f = k2*32 + lane;             // float4 idx in warp's 8x64 block
        int row = w*8 + (f >> 4), c4 = (f & 15) * 4;
        CP_ASYNC16(es_sa + (unsigned)(row*68 + c4)*4, ebase + (size_t)row*64 + c4);
    }
    CP_COMMIT();

    #pragma unroll
    for (int k = 0; k < 4; k++) ps[t + k*128] = g_p[i*512 + t + k*128];
    // prefetch tile-0 base logits
    float cur0 = g_sc[((size_t)(2*cq)*L + i)*L + jl];
    float cur1 = g_sc[((size_t)(2*cq + 1)*L + i)*L + jl];
    __syncthreads();    // ps visible to all warps

    float sacc0 = 0.f, sacc1 = 0.f;
    float wacc[16];
    #pragma unroll
    for (int n = 0; n < 16; n++) wacc[n] = 0.f;
    float4 va = make_float4(0.f,0.f,0.f,0.f), vb = make_float4(0.f,0.f,0.f,0.f);

    const float4* psf = (const float4*)ps;

    for (int tile = 0; tile < 16; tile++) {
        int b = tile & 1, j0 = tile * TROWS;
        CP_WAIT0();
        __syncwarp();     // prev phase-C reads of pes done before overwrite

        if (tile < 15) {  // prefetch own rows of next tile into other buffer
            #pragma unroll
            for (int k2 = 0; k2 < 4; k2++) {
                int f = k2*32 + lane;
                int row = w*8 + (f >> 4), c4 = (f & 15) * 4;
                CP_ASYNC16(es_sa + (unsigned)((b^1)*TSTRIDE + row*68 + c4)*4,
                           ebase + (size_t)(j0 + TROWS)*64 + (size_t)row*64 + c4);
            }
            CP_COMMIT();
        }
        // prefetch next tile's base logits (hide LDG latency under compute)
        float nxt0 = 0.f, nxt1 = 0.f;
        if (tile < 15) {
            nxt0 = g_sc[((size_t)(2*cq)*L + i)*L + (j0 + TROWS + jl)];
            nxt1 = g_sc[((size_t)(2*cq + 1)*L + i)*L + (j0 + TROWS + jl)];
        }

        // ---- Phase A: scores for row jl, ALL heads. Quarter cq of 64 cols.
        {
            const float4* er = (const float4*)&espool[b*TSTRIDE + jl*68];
            float4 ev0 = er[cq*4 + 0], ev1 = er[cq*4 + 1];
            float4 ev2 = er[cq*4 + 2], ev3 = er[cq*4 + 3];
            float accs[8];
            #pragma unroll
            for (int n = 0; n < 8; n++) {
                const float4* pq = psf + n*16 + cq*4;
                float4 p0 = pq[0], p1 = pq[1], p2 = pq[2], p3 = pq[3];
                float a = 0.f;
                a = fmaf(ev0.x, p0.x, a); a = fmaf(ev0.y, p0.y, a);
                a = fmaf(ev0.z, p0.z, a); a = fmaf(ev0.w, p0.w, a);
                a = fmaf(ev1.x, p1.x, a); a = fmaf(ev1.y, p1.y, a);
                a = fmaf(ev1.z, p1.z, a); a = fmaf(ev1.w, p1.w, a);
                a = fmaf(ev2.x, p2.x, a); a = fmaf(ev2.y, p2.y, a);
                a = fmaf(ev2.z, p2.z, a); a = fmaf(ev2.w, p2.w, a);
                a = fmaf(ev3.x, p3.x, a); a = fmaf(ev3.y, p3.y, a);
                a = fmaf(ev3.z, p3.z, a); a = fmaf(ev3.w, p3.w, a);
                accs[n] = a;
            }
            #pragma unroll
            for (int off = 8; off <= 16; off <<= 1)
                #pragma unroll
                for (int n = 0; n < 8; n++)
                    accs[n] += __shfl_xor_sync(0xffffffffu, accs[n], off);
            float pe0 = __expf(accs[2*cq] + cur0);
            float pe1 = __expf(accs[2*cq + 1] + cur1);
            sacc0 += pe0; sacc1 += pe1;
            *(float2*)&pes[jl*8 + 2*cq] = make_float2(pe0, pe1);
            pes_t[(2*cq)*TROWS + jl]     = pe0;
            pes_t[(2*cq + 1)*TROWS + jl] = pe1;
        }
        cur0 = nxt0; cur1 = nxt1;
        __syncwarp();     // pes rows of this warp visible warp-wide

        // ---- Phase C: edge-weights + attn@v over OWN 8 rows
        float2 pa2 = make_float2(0.f,0.f), pb2 = make_float2(0.f,0.f);
        #pragma unroll
        for (int q = 0; q < 8; q++) {
            int jj = w*8 + q;
            const float* prow = &pes[jj*8];
            float2 p01 = *(const float2*)&prow[0];
            float2 p23 = *(const float2*)&prow[2];
            float2 p45 = *(const float2*)&prow[4];
            float2 p67 = *(const float2*)&prow[6];
            float2 ee = *(const float2*)&espool[b*TSTRIDE + jj*68 + 2*lane];
            wacc[0]  = fmaf(p01.x, ee.x, wacc[0]);  wacc[1]  = fmaf(p01.x, ee.y, wacc[1]);
            wacc[2]  = fmaf(p01.y, ee.x, wacc[2]);  wacc[3]  = fmaf(p01.y, ee.y, wacc[3]);
            wacc[4]  = fmaf(p23.x, ee.x, wacc[4]);  wacc[5]  = fmaf(p23.x, ee.y, wacc[5]);
            wacc[6]  = fmaf(p23.y, ee.x, wacc[6]);  wacc[7]  = fmaf(p23.y, ee.y, wacc[7]);
            wacc[8]  = fmaf(p45.x, ee.x, wacc[8]);  wacc[9]  = fmaf(p45.x, ee.y, wacc[9]);
            wacc[10] = fmaf(p45.y, ee.x, wacc[10]); wacc[11] = fmaf(p45.y, ee.y, wacc[11]);
            wacc[12] = fmaf(p67.x, ee.x, wacc[12]); wacc[13] = fmaf(p67.x, ee.y, wacc[13]);
            wacc[14] = fmaf(p67.y, ee.x, wacc[14]); wacc[15] = fmaf(p67.y, ee.y, wacc[15]);
            // attn@v: pe scalars via transposed layout (broadcast LDS.64 per 2q)
            if ((q & 1) == 0) {
                pa2 = *(const float2*)&pes_t[vh*TROWS + jj];
                pb2 = *(const float2*)&pes_t[(vh + 4)*TROWS + jj];
            }
            float pva = (q & 1) ? pa2.y : pa2.x;
            float pvb = (q & 1) ? pb2.y : pb2.x;
            const float4* vv = (const float4*)&g_v[(size_t)(j0 + jj)*DE];
            float4 v0 = vv[lane];
            float4 v1 = vv[lane + 32];
            va.x = fmaf(pva, v0.x, va.x); va.y = fmaf(pva, v0.y, va.y);
            va.z = fmaf(pva, v0.z, va.z); va.w = fmaf(pva, v0.w, va.w);
            vb.x = fmaf(pvb, v1.x, vb.x); vb.y = fmaf(pvb, v1.y, vb.y);
            vb.z = fmaf(pvb, v1.z, vb.z); vb.w = fmaf(pvb, v1.w, vb.w);
        }
    }

    // ---------------- Tail: cross-warp reductions + projections
    __syncthreads();
    float* wpart = espool;            // [4 warps][8 heads][64 c] = 2048 floats
    float* vred  = espool + 2048;     // [4 warps][256]           = 1024
    float* stmp  = espool + 3072;     // [8 heads][32]            = 256
    float* att   = espool + 3328;     // [256]
    float* opart = espool + 3584;     // [2][64]                  = 128
    float* wfin  = espool + 3712;     // [8 heads][64]            = 512

    #pragma unroll
    for (int n = 0; n < 8; n++)
        *(float2*)&wpart[(w*8 + n)*64 + 2*lane] = make_float2(wacc[2*n], wacc[2*n + 1]);
    *(float4*)&vred[w*256 + 4*lane]       = va;
    *(float4*)&vred[w*256 + 128 + 4*lane] = vb;
    stmp[(2*cq)*TROWS + jl]     = sacc0;
    stmp[(2*cq + 1)*TROWS + jl] = sacc1;
    __syncthreads();

    {   // softmax denominators: warp w reduces heads w and w+4
        float sv0 = stmp[w*TROWS + lane];            // lane < 32 covers 32 j's
        float sv1 = stmp[(w + 4)*TROWS + lane];
        #pragma unroll
        for (int off = 16; off; off >>= 1) {
            sv0 += __shfl_xor_sync(0xffffffffu, sv0, off);
            sv1 += __shfl_xor_sync(0xffffffffu, sv1, off);
        }
        if (lane == 0) { svals[w] = sv0; svals[w + 4] = sv1; }
    }
    #pragma unroll
    for (int k = 0; k < 4; k++) {   // wfin[n][c] = sum over 4 warps
        int idx = t + k*128;
        int n0 = idx >> 6, c0 = idx & 63;
        float f0 = 0.f;
        #pragma unroll
        for (int sw = 0; sw < 4; sw++) f0 += wpart[(sw*8 + n0)*64 + c0];
        wfin[n0*64 + c0] = f0;
    }
    __syncthreads();

    #pragma unroll
    for (int k = 0; k < 2; k++) {   // att[tt] = (attn@v + edge proj)/s
        int tt = t + k*128;
        int n = tt >> 5;
        const float* wn = &wfin[n*64];
        float e0 = 0.f, e1 = 0.f;
        #pragma unroll
        for (int c = 0; c < 64; c += 2) {
            e0 = fmaf(wn[c],     We[c*DE + tt],       e0);
            e1 = fmaf(wn[c + 1], We[(c + 1)*DE + tt], e1);
        }
        float vsum = vred[tt] + vred[256 + tt] + vred[512 + tt] + vred[768 + tt];
        att[tt] = (vsum + e0 + e1) / svals[n];
    }
    __syncthreads();

    {   // out = att@Wo + bo : 64 outputs x 2-way k-split
        int o = t & 63, kq = t >> 6;
        float a = 0.f;
        #pragma unroll
        for (int kk = 0; kk < 128; kk++) {
            int k = kq*128 + kk;
            a = fmaf(att[k], Wo[k*DO + o], a);
        }
        opart[kq*64 + o] = a;
    }
    __syncthreads();
    if (t < DO)
        out[i*DO + t] = bo[t] + opart[t] + opart[64 + t];
}

// ---------------------------------------------------------------------------
extern "C" void kernel_launch(void* const* d_in, const int* in_sizes, int n_in,
                              void* d_out, int out_size) {
    const float* x  = (const float*)d_in[0];
    const float* e  = (const float*)d_in[1];
    const float* Wq = (const float*)d_in[2];
    const float* Wk = (const float*)d_in[3];
    const float* Wv = (const float*)d_in[4];
    const float* We = (const float*)d_in[5];
    const float* Wo = (const float*)d_in[6];
    const float* bo = (const float*)d_in[7];
    float* out = (float*)d_out;

    proj_kernel<<<dim3(4, 8, 3), 256>>>(x, Wq, Wk, Wv);
    p_kernel<<<dim3(8, 8), 256>>>(We);
    qk_kernel<<<dim3(16, 16, 8), 256>>>();
    attn_kernel<<<512, 128>>>(e, We, Wo, bo, out);
}